// round 15
// baseline (speedup 1.0000x reference)
#include <cuda_runtime.h>
#include <stdint.h>

#define IMG_H 2048
#define IMG_W 2048
#define NPIX (IMG_H * IMG_W)
#define NT 8
#define NBINS 256

__device__ unsigned int g_hist[NT * NT * NBINS];
__device__ float g_lut[NT * NT * NBINS];

// fast cbrt for v in (0, ~1.1]: ex2(lg2(v)/3) via MUFU. ~1e-6 rel, 3 instrs.
__device__ __forceinline__ float cbrt_fast(float v) {
    float l, r;
    asm("lg2.approx.f32 %0, %1;" : "=f"(l) : "f"(v));
    l *= (1.0f / 3.0f);
    asm("ex2.approx.f32 %0, %1;" : "=f"(r) : "f"(l));
    return r;
}

__device__ __forceinline__ float f_lab(float v) {
    return (v > 0.008856f) ? cbrt_fast(v) : (7.787f * v + 16.0f / 116.0f);
}

__device__ __forceinline__ void griddep_wait() {
    asm volatile("griddepcontrol.wait;" ::: "memory");
}
__device__ __forceinline__ void griddep_launch() {
    asm volatile("griddepcontrol.launch_dependents;" ::: "memory");
}
__device__ __forceinline__ void cp_async16(uint32_t dst_smem, const void* src) {
    asm volatile("cp.async.cg.shared.global [%0], [%1], 16;"
                 :: "r"(dst_smem), "l"(src));
}

// ---------------------------------------------------------------------------
// Kernel 1: per-tile histograms, burst-staged cp.async.
// Block = 256 thr covers 4 rows x 512 cols (2 x-tiles); grid (512,4) = 2048.
// ONE cp.async burst (1536 x 16B), one wait, one sync, then pure compute +
// shared atomics. Latency hiding is inter-block: 7 resident blocks/SM
// (smem 32KB, regs capped 36) are in different load/compute phases, so the
// SM always has a block bursting loads. Per-warp hist replicas kill
// cross-warp ATOMS serialization. g_hist zero on entry (k_lut re-zeroes).
// ---------------------------------------------------------------------------
__global__ __launch_bounds__(256, 7) void k_hist(const float* __restrict__ rp,
                                                 const float* __restrict__ gp,
                                                 const float* __restrict__ bp) {
    __shared__ unsigned int sh[2][4][NBINS];         // [tile][replica][bin] 8KB
    __shared__ alignas(16) float buf[4][3][512];     // [row][chan][col] 24KB
    const int tid = threadIdx.x;
    for (int i = tid; i < 2 * 4 * NBINS; i += 256) ((unsigned*)sh)[i] = 0u;
    // (visibility of the zeroes is covered by the __syncthreads after the wait)

    const int colbase = blockIdx.y * 512;            // 0..3 -> col chunk
    const int row0 = blockIdx.x * 4;                 // 0..511 -> 4-row band

    // single burst: 1536 16B chunks = 4 rows x 3 chans x 128 chunks
#pragma unroll
    for (int i = 0; i < 6; ++i) {
        const int j = tid + 256 * i;
        const int c16 = j & 127;                     // 16B chunk within row
        const int rc = j >> 7;                       // 0..11
        const int chan = rc % 3;
        const int row = rc / 3;
        const float* src = (chan == 0 ? rp : (chan == 1 ? gp : bp)) +
                           (row0 + row) * IMG_W + colbase + c16 * 4;
        cp_async16((uint32_t)__cvta_generic_to_shared(&buf[row][chan][c16 * 4]),
                   src);
    }
    asm volatile("cp.async.commit_group;" ::: "memory");
    asm volatile("cp.async.wait_group 0;" ::: "memory");
    __syncthreads();

    const int wid = tid >> 5;                        // 0..7
    const int tl = tid >> 7;                         // x-tile of cols [2t,2t+1]
    unsigned int* __restrict__ h = sh[tl][wid & 3];  // unique replica per warp

#pragma unroll
    for (int r = 0; r < 4; ++r) {
        const float2 R = *(const float2*)&buf[r][0][tid * 2];
        const float2 G = *(const float2*)&buf[r][1][tid * 2];
        const float2 B = *(const float2*)&buf[r][2][tid * 2];
#pragma unroll
        for (int k = 0; k < 2; ++k) {
            const float Y = 0.212671f * (&R.x)[k] + 0.715160f * (&G.x)[k] +
                            0.072169f * (&B.x)[k];
            int v = (int)rintf(fmaf(f_lab(Y), 295.8f, -40.8f)); // (116f-16)*2.55
            v = min(max(v, 0), 255);
            atomicAdd(&h[v], 1u);
        }
    }
    __syncthreads();
    griddep_launch();                                // let k_lut blocks spin up

    const int ty = blockIdx.x >> 6;                  // tile row (64 bands/tile)
    for (int i = tid; i < 2 * NBINS; i += 256) {
        const int t = i >> 8, bin = i & 255;
        const unsigned v = sh[t][0][bin] + sh[t][1][bin] +
                           sh[t][2][bin] + sh[t][3][bin];
        if (v) atomicAdd(&g_hist[(ty * NT + blockIdx.y * 2 + t) * NBINS + bin], v);
    }
}

// ---------------------------------------------------------------------------
// Kernel 2: clip + redistribute + cdf -> LUT. PDL secondary. Kogge-Stone
// scan (BIT-EXACT: partial sums are multiples of 2^-8 bounded by 2^16).
// Re-zeroes g_hist for the next graph replay.
// ---------------------------------------------------------------------------
__global__ __launch_bounds__(NBINS) void k_lut() {
    __shared__ float wsum[8];
    __shared__ unsigned int s_ex;
    const int t = threadIdx.x, b = blockIdx.x;
    const int lane = t & 31, warp = t >> 5;
    if (t == 0) s_ex = 0u;
    __syncthreads();

    griddep_wait();                              // k_hist stores now visible

    const unsigned h = g_hist[b * NBINS + t];
    g_hist[b * NBINS + t] = 0u;                  // reset for next replay
    const unsigned over = (h > 2560u) ? (h - 2560u) : 0u;  // clip = 10*65536/256
    if (over) atomicAdd(&s_ex, over);
    __syncthreads();

    float v = (float)min(h, 2560u) + (float)s_ex * (1.0f / 256.0f);

#pragma unroll
    for (int off = 1; off < 32; off <<= 1) {
        const float n = __shfl_up_sync(0xffffffffu, v, off);
        if (lane >= off) v += n;
    }
    if (lane == 31) wsum[warp] = v;
    __syncthreads();
    if (warp == 0 && lane < 8) {
        float w = wsum[lane];
#pragma unroll
        for (int off = 1; off < 8; off <<= 1) {
            const float n = __shfl_up_sync(0x000000ffu, w, off);
            if (lane >= off) w += n;
        }
        wsum[lane] = w;
    }
    __syncthreads();
    const float cdf = v + (warp > 0 ? wsum[warp - 1] : 0.0f);

    float lut = rintf(cdf * (255.0f / 65536.0f));
    g_lut[b * NBINS + t] = fminf(fmaxf(lut, 0.0f), 255.0f);
    griddep_launch();                            // let k_apply blocks spin up
}

// ---------------------------------------------------------------------------
// Kernel 3: apply. Block = 256 thr covers 4 rows x 512 cols, 4 px/thread.
// Grid = (512, 4) = 2048 blocks. PDL secondary: index math during k_lut's
// drain; griddep_wait gates only the slut loads. Algebraic folds:
//   a/500 == fX-fY, b/200 == fY-fZ => fx2 = fX + d, fz2 = fZ + d;
//   white point folded into input rows and output columns; .SAT saturate.
// ---------------------------------------------------------------------------
__global__ __launch_bounds__(256, 6) void k_apply(const float* __restrict__ in,
                                                  float* __restrict__ out) {
    __shared__ float2 slut[4][NBINS];
    const int tid = threadIdx.x;
    const int bx = blockIdx.y;       // x-chunk 0..3
    const int by = blockIdx.x;       // y-band 0..511
    const int row_base = by * 4;

    const float fy0 = fminf(fmaxf((row_base + 0.5f) * (1.0f / 256.0f) - 0.5f, 0.0f), 7.0f);
    const int yt0 = (int)floorf(fy0);
    const int yt1 = min(yt0 + 1, NT - 1);

    const int col0 = bx * 512 + (tid & 127) * 4;
    const int row0 = row_base + (tid >> 7);

    const float fxg = fminf(fmaxf((col0 + 0.5f) * (1.0f / 256.0f) - 0.5f, 0.0f), 7.0f);
    const int x0c = (int)floorf(fxg);
    const int xs0 = x0c - (bx * 2 - 1);               // slot in [0,3]
    const int xs1 = min(x0c + 1, NT - 1) - (bx * 2 - 1);

    float wxv[4];
#pragma unroll
    for (int k = 0; k < 4; ++k) {
        const float fx = fminf(fmaxf((col0 + k + 0.5f) * (1.0f / 256.0f) - 0.5f, 0.0f), 7.0f);
        wxv[k] = fx - (float)x0c;
    }

    griddep_wait();                              // k_lut stores now visible

#pragma unroll
    for (int s = 0; s < 4; ++s) {
        const int xt = min(max(bx * 2 - 1 + s, 0), NT - 1);
        slut[s][tid] = make_float2(g_lut[(yt0 * NT + xt) * NBINS + tid],
                                   g_lut[(yt1 * NT + xt) * NBINS + tid]);
    }
    __syncthreads();

    const float* __restrict__ rp = in;
    const float* __restrict__ gp = in + NPIX;
    const float* __restrict__ bp = in + 2 * NPIX;

#pragma unroll
    for (int r = 0; r < 2; ++r) {
        const int row = row0 + 2 * r;
        const int idx = row * IMG_W + col0;
        const float4 R = *(const float4*)(rp + idx);
        const float4 G = *(const float4*)(gp + idx);
        const float4 B = *(const float4*)(bp + idx);

        const float fyr = fminf(fmaxf((row + 0.5f) * (1.0f / 256.0f) - 0.5f, 0.0f), 7.0f);
        const float wy = fyr - (float)yt0;

        float4 Ro, Go, Bo;
#pragma unroll
        for (int k = 0; k < 4; ++k) {
            const float rr = (&R.x)[k], gg = (&G.x)[k], bb = (&B.x)[k];

            // input matrix with white point pre-divided into rows 0 and 2
            const float Xv = 0.4339530f * rr + 0.3762217f * gg + 0.1898289f * bb;
            const float Yv = 0.2126710f * rr + 0.7151600f * gg + 0.0721690f * bb;
            const float Zv = 0.0177580f * rr + 0.1094767f * gg + 0.8727647f * bb;
            const float fX = f_lab(Xv), fY = f_lab(Yv), fZ = f_lab(Zv);

            int l8 = (int)rintf(fmaf(fY, 295.8f, -40.8f));   // (116 fY - 16)*2.55
            l8 = min(max(l8, 0), 255);

            const float2 A = slut[xs0][l8];
            const float2 Bt = slut[xs1][l8];
            const float v0 = fmaf(wy, A.y - A.x, A.x);
            const float v1 = fmaf(wy, Bt.y - Bt.x, Bt.x);
            const float lutv = fmaf(wxv[k], v1 - v0, v0);

            const float fy2 = fmaf(lutv, 100.0f / (255.0f * 116.0f), 16.0f / 116.0f);
            const float d = fy2 - fY;
            const float fx2 = fX + d;
            const float fz2 = fZ + d;

            const float x3 = fx2 * fx2 * fx2;
            const float y3 = fy2 * fy2 * fy2;
            const float z3 = fz2 * fz2 * fz2;
            const float Xo = (x3 > 0.008856f) ? x3
                             : fmaf(fx2, 0.1284191f, -0.0177129f);
            const float Yo = (y3 > 0.008856f) ? y3
                             : fmaf(fy2, 0.1284191f, -0.0177129f);
            const float Zo = (z3 > 0.008856f) ? z3
                             : fmaf(fz2, 0.1284191f, -0.0177129f);

            (&Ro.x)[k] = __saturatef( 3.0799327f * Xo - 1.537150f * Yo - 0.5427823f * Zo);
            (&Go.x)[k] = __saturatef(-0.9212352f * Xo + 1.875992f * Yo + 0.0452442f * Zo);
            (&Bo.x)[k] = __saturatef( 0.0528910f * Xo - 0.204043f * Yo + 1.1511516f * Zo);
        }
        *(float4*)(out + idx)            = Ro;
        *(float4*)(out + NPIX + idx)     = Go;
        *(float4*)(out + 2 * NPIX + idx) = Bo;
    }
}

// ---------------------------------------------------------------------------
extern "C" void kernel_launch(void* const* d_in, const int* in_sizes, int n_in,
                              void* d_out, int out_size) {
    const float* in = (const float*)d_in[0];
    float* out = (float*)d_out;
    (void)in_sizes; (void)n_in; (void)out_size;

    k_hist<<<dim3(512, 4), 256>>>(in, in + NPIX, in + 2 * NPIX);

    cudaLaunchAttribute attr[1];
    attr[0].id = cudaLaunchAttributeProgrammaticStreamSerialization;
    attr[0].val.programmaticStreamSerializationAllowed = 1;

    {
        cudaLaunchConfig_t cfg = {};
        cfg.gridDim = dim3(NT * NT);
        cfg.blockDim = dim3(NBINS);
        cfg.attrs = attr;
        cfg.numAttrs = 1;
        cudaLaunchKernelEx(&cfg, k_lut);
    }
    {
        cudaLaunchConfig_t cfg = {};
        cfg.gridDim = dim3(512, 4);
        cfg.blockDim = dim3(256);
        cfg.attrs = attr;
        cfg.numAttrs = 1;
        cudaLaunchKernelEx(&cfg, k_apply, in, out);
    }
}

// round 16
// speedup vs baseline: 1.0691x; 1.0691x over previous
#include <cuda_runtime.h>
#include <cuda_fp16.h>
#include <stdint.h>

#define IMG_H 2048
#define IMG_W 2048
#define NPIX (IMG_H * IMG_W)
#define NT 8
#define NBINS 256

__device__ unsigned int g_hist[NT * NT * NBINS];
__device__ float g_lut[NT * NT * NBINS];

// fast cbrt for v in (0, ~1.1]: ex2(lg2(v)/3) via MUFU. ~1e-6 rel, 3 instrs.
__device__ __forceinline__ float cbrt_fast(float v) {
    float l, r;
    asm("lg2.approx.f32 %0, %1;" : "=f"(l) : "f"(v));
    l *= (1.0f / 3.0f);
    asm("ex2.approx.f32 %0, %1;" : "=f"(r) : "f"(l));
    return r;
}

__device__ __forceinline__ float f_lab(float v) {
    return (v > 0.008856f) ? cbrt_fast(v) : (7.787f * v + 16.0f / 116.0f);
}

__device__ __forceinline__ void griddep_wait() {
    asm volatile("griddepcontrol.wait;" ::: "memory");
}

// ---------------------------------------------------------------------------
// Kernel 1: per-tile histograms (measured-best config). Block = 256 thr
// covers 8 rows x 512 cols (2 x-tiles); grid (256,4) = 1024 blocks; (256,8)
// caps regs at 32 -> 8 blocks/SM. Per-warp hist replicas kill cross-warp
// ATOMS serialization. g_hist zero on entry (k_lut re-zeroes each run).
// ---------------------------------------------------------------------------
__global__ __launch_bounds__(256, 8) void k_hist(const float* __restrict__ rp,
                                                 const float* __restrict__ gp,
                                                 const float* __restrict__ bp) {
    __shared__ unsigned int sh[2][4][NBINS];     // [tile][replica][bin] 8KB
    const int tid = threadIdx.x;
    for (int i = tid; i < 2 * 4 * NBINS; i += 256) ((unsigned*)sh)[i] = 0u;
    __syncthreads();

    const int col0 = blockIdx.y * 512 + (tid & 127) * 4;   // blockIdx.y in 0..3
    const int row0 = blockIdx.x * 8 + (tid >> 7);          // blockIdx.x in 0..255
    const int wid = tid >> 5;                    // 0..7
    const int tl = (wid >> 1) & 1;               // x-tile 0/1 (matches columns)
    const int rep = (wid & 1) | ((wid >> 2) << 1);   // unique replica per warp
    unsigned int* __restrict__ h = sh[tl][rep];

#pragma unroll
    for (int r = 0; r < 4; ++r) {
        const int base = (row0 + 2 * r) * IMG_W + col0;
        const float4 R = *(const float4*)(rp + base);
        const float4 G = *(const float4*)(gp + base);
        const float4 B = *(const float4*)(bp + base);
#pragma unroll
        for (int k = 0; k < 4; ++k) {
            const float Y = 0.212671f * (&R.x)[k] + 0.715160f * (&G.x)[k] +
                            0.072169f * (&B.x)[k];
            int v = (int)rintf(fmaf(f_lab(Y), 295.8f, -40.8f)); // (116f-16)*2.55
            v = min(max(v, 0), 255);
            atomicAdd(&h[v], 1u);
        }
    }
    __syncthreads();

    const int ty = blockIdx.x >> 5;              // tile row (8-row bands, 32/tile)
    for (int i = tid; i < 2 * NBINS; i += 256) {
        const int t = i >> 8, bin = i & 255;
        const unsigned v = sh[t][0][bin] + sh[t][1][bin] +
                           sh[t][2][bin] + sh[t][3][bin];
        if (v) atomicAdd(&g_hist[(ty * NT + blockIdx.y * 2 + t) * NBINS + bin], v);
    }
}

// ---------------------------------------------------------------------------
// Kernel 2: clip + redistribute + cdf -> LUT. PDL secondary. Kogge-Stone
// scan (BIT-EXACT: partial sums are multiples of 2^-8 bounded by 2^16).
// Re-zeroes g_hist for the next graph replay.
// ---------------------------------------------------------------------------
__global__ __launch_bounds__(NBINS) void k_lut() {
    __shared__ float wsum[8];
    __shared__ unsigned int s_ex;
    const int t = threadIdx.x, b = blockIdx.x;
    const int lane = t & 31, warp = t >> 5;
    if (t == 0) s_ex = 0u;
    __syncthreads();

    griddep_wait();                              // k_hist stores now visible

    const unsigned h = g_hist[b * NBINS + t];
    g_hist[b * NBINS + t] = 0u;                  // reset for next replay
    const unsigned over = (h > 2560u) ? (h - 2560u) : 0u;  // clip = 10*65536/256
    if (over) atomicAdd(&s_ex, over);
    __syncthreads();

    float v = (float)min(h, 2560u) + (float)s_ex * (1.0f / 256.0f);

#pragma unroll
    for (int off = 1; off < 32; off <<= 1) {
        const float n = __shfl_up_sync(0xffffffffu, v, off);
        if (lane >= off) v += n;
    }
    if (lane == 31) wsum[warp] = v;
    __syncthreads();
    if (warp == 0 && lane < 8) {
        float w = wsum[lane];
#pragma unroll
        for (int off = 1; off < 8; off <<= 1) {
            const float n = __shfl_up_sync(0x000000ffu, w, off);
            if (lane >= off) w += n;
        }
        wsum[lane] = w;
    }
    __syncthreads();
    const float cdf = v + (warp > 0 ? wsum[warp - 1] : 0.0f);

    float lut = rintf(cdf * (255.0f / 65536.0f));
    g_lut[b * NBINS + t] = fminf(fmaxf(lut, 0.0f), 255.0f);
}

// ---------------------------------------------------------------------------
// Kernel 3: apply. Block = 256 thr covers 4 rows x 512 cols, 4 px/thread.
// Grid = (512, 4) = 2048 blocks. PDL secondary. LUTs now stored as half2
// (y0,y1) pairs in shared: values are exact integers 0..255, so fp16 is
// LOSSLESS and the fp32 interpolation after __half22float2 is bit-identical
// to the float2 version — but LDS entries shrink to 4B, using all 32 banks
// (float2 used 16) and halving LDS traffic. Algebraic folds as before.
// ---------------------------------------------------------------------------
__global__ __launch_bounds__(256, 6) void k_apply(const float* __restrict__ in,
                                                  float* __restrict__ out) {
    __shared__ __half2 slut[4][NBINS];
    const int tid = threadIdx.x;
    const int bx = blockIdx.y;       // x-chunk 0..3
    const int by = blockIdx.x;       // y-band 0..511
    const int row_base = by * 4;

    const float fy0 = fminf(fmaxf((row_base + 0.5f) * (1.0f / 256.0f) - 0.5f, 0.0f), 7.0f);
    const int yt0 = (int)floorf(fy0);
    const int yt1 = min(yt0 + 1, NT - 1);

    const int col0 = bx * 512 + (tid & 127) * 4;
    const int row0 = row_base + (tid >> 7);

    const float fxg = fminf(fmaxf((col0 + 0.5f) * (1.0f / 256.0f) - 0.5f, 0.0f), 7.0f);
    const int x0c = (int)floorf(fxg);
    const int xs0 = x0c - (bx * 2 - 1);               // slot in [0,3]
    const int xs1 = min(x0c + 1, NT - 1) - (bx * 2 - 1);

    float wxv[4];
#pragma unroll
    for (int k = 0; k < 4; ++k) {
        const float fx = fminf(fmaxf((col0 + k + 0.5f) * (1.0f / 256.0f) - 0.5f, 0.0f), 7.0f);
        wxv[k] = fx - (float)x0c;
    }

    griddep_wait();                              // k_lut stores now visible

#pragma unroll
    for (int s = 0; s < 4; ++s) {
        const int xt = min(max(bx * 2 - 1 + s, 0), NT - 1);
        slut[s][tid] = __floats2half2_rn(g_lut[(yt0 * NT + xt) * NBINS + tid],
                                         g_lut[(yt1 * NT + xt) * NBINS + tid]);
    }
    __syncthreads();

    const float* __restrict__ rp = in;
    const float* __restrict__ gp = in + NPIX;
    const float* __restrict__ bp = in + 2 * NPIX;

#pragma unroll
    for (int r = 0; r < 2; ++r) {
        const int row = row0 + 2 * r;
        const int idx = row * IMG_W + col0;
        const float4 R = *(const float4*)(rp + idx);
        const float4 G = *(const float4*)(gp + idx);
        const float4 B = *(const float4*)(bp + idx);

        const float fyr = fminf(fmaxf((row + 0.5f) * (1.0f / 256.0f) - 0.5f, 0.0f), 7.0f);
        const float wy = fyr - (float)yt0;

        float4 Ro, Go, Bo;
#pragma unroll
        for (int k = 0; k < 4; ++k) {
            const float rr = (&R.x)[k], gg = (&G.x)[k], bb = (&B.x)[k];

            // input matrix with white point pre-divided into rows 0 and 2
            const float Xv = 0.4339530f * rr + 0.3762217f * gg + 0.1898289f * bb;
            const float Yv = 0.2126710f * rr + 0.7151600f * gg + 0.0721690f * bb;
            const float Zv = 0.0177580f * rr + 0.1094767f * gg + 0.8727647f * bb;
            const float fX = f_lab(Xv), fY = f_lab(Yv), fZ = f_lab(Zv);

            int l8 = (int)rintf(fmaf(fY, 295.8f, -40.8f));   // (116 fY - 16)*2.55
            l8 = min(max(l8, 0), 255);

            const float2 A = __half22float2(slut[xs0][l8]);
            const float2 Bt = __half22float2(slut[xs1][l8]);
            const float v0 = fmaf(wy, A.y - A.x, A.x);
            const float v1 = fmaf(wy, Bt.y - Bt.x, Bt.x);
            const float lutv = fmaf(wxv[k], v1 - v0, v0);

            const float fy2 = fmaf(lutv, 100.0f / (255.0f * 116.0f), 16.0f / 116.0f);
            const float d = fy2 - fY;
            const float fx2 = fX + d;
            const float fz2 = fZ + d;

            const float x3 = fx2 * fx2 * fx2;
            const float y3 = fy2 * fy2 * fy2;
            const float z3 = fz2 * fz2 * fz2;
            const float Xo = (x3 > 0.008856f) ? x3
                             : fmaf(fx2, 0.1284191f, -0.0177129f);
            const float Yo = (y3 > 0.008856f) ? y3
                             : fmaf(fy2, 0.1284191f, -0.0177129f);
            const float Zo = (z3 > 0.008856f) ? z3
                             : fmaf(fz2, 0.1284191f, -0.0177129f);

            (&Ro.x)[k] = __saturatef( 3.0799327f * Xo - 1.537150f * Yo - 0.5427823f * Zo);
            (&Go.x)[k] = __saturatef(-0.9212352f * Xo + 1.875992f * Yo + 0.0452442f * Zo);
            (&Bo.x)[k] = __saturatef( 0.0528910f * Xo - 0.204043f * Yo + 1.1511516f * Zo);
        }
        *(float4*)(out + idx)            = Ro;
        *(float4*)(out + NPIX + idx)     = Go;
        *(float4*)(out + 2 * NPIX + idx) = Bo;
    }
}

// ---------------------------------------------------------------------------
extern "C" void kernel_launch(void* const* d_in, const int* in_sizes, int n_in,
                              void* d_out, int out_size) {
    const float* in = (const float*)d_in[0];
    float* out = (float*)d_out;
    (void)in_sizes; (void)n_in; (void)out_size;

    k_hist<<<dim3(256, 4), 256>>>(in, in + NPIX, in + 2 * NPIX);

    cudaLaunchAttribute attr[1];
    attr[0].id = cudaLaunchAttributeProgrammaticStreamSerialization;
    attr[0].val.programmaticStreamSerializationAllowed = 1;

    {
        cudaLaunchConfig_t cfg = {};
        cfg.gridDim = dim3(NT * NT);
        cfg.blockDim = dim3(NBINS);
        cfg.attrs = attr;
        cfg.numAttrs = 1;
        cudaLaunchKernelEx(&cfg, k_lut);
    }
    {
        cudaLaunchConfig_t cfg = {};
        cfg.gridDim = dim3(512, 4);
        cfg.blockDim = dim3(256);
        cfg.attrs = attr;
        cfg.numAttrs = 1;
        cudaLaunchKernelEx(&cfg, k_apply, in, out);
    }
}